// round 1
// baseline (speedup 1.0000x reference)
#include <cuda_runtime.h>
#include <math.h>

#define BB 4
#define NN 1024
#define DD 1024
#define EE 32
#define HHH 4096

// ---------------- scratch (device globals; no allocation allowed) ----------
__device__ float g_q[EE * DD];                 // 128 KB
__device__ float g_logits[BB * NN * EE];       // 512 KB
__device__ float g_combine[BB * NN * EE];      // 512 KB
__device__ float g_dispatch[BB * NN * EE];     // 512 KB
__device__ float g_slots_part[4 * BB * EE * DD]; // 2 MB
__device__ float g_slots[BB * EE * DD];        // 512 KB
__device__ float g_h[BB * EE * HHH];           // 2 MB
__device__ float g_eout_part[2 * BB * EE * DD]; // 1 MB
__device__ float g_eout[BB * EE * DD];         // 512 KB
__device__ float g_part_cw1[128];
__device__ float g_part_cw2[128];
__device__ float g_part_dw[128];

// ---------------- reduction helpers ----------------
__device__ __forceinline__ float warpSum(float v) {
    #pragma unroll
    for (int o = 16; o; o >>= 1) v += __shfl_xor_sync(0xffffffffu, v, o);
    return v;
}
__device__ __forceinline__ float warpMax(float v) {
    #pragma unroll
    for (int o = 16; o; o >>= 1) v = fmaxf(v, __shfl_xor_sync(0xffffffffu, v, o));
    return v;
}
__device__ float blockSum(float v) {
    __shared__ float sh[32];
    int lane = threadIdx.x & 31, wid = threadIdx.x >> 5;
    int nw = (blockDim.x + 31) >> 5;
    v = warpSum(v);
    if (lane == 0) sh[wid] = v;
    __syncthreads();
    float r = (threadIdx.x < (unsigned)nw) ? sh[threadIdx.x] : 0.f;
    if (wid == 0) {
        r = warpSum(r);
        if (lane == 0) sh[0] = r;
    }
    __syncthreads();
    r = sh[0];
    __syncthreads();
    return r;
}
__device__ float blockMax(float v) {
    __shared__ float sh[32];
    int lane = threadIdx.x & 31, wid = threadIdx.x >> 5;
    int nw = (blockDim.x + 31) >> 5;
    v = warpMax(v);
    if (lane == 0) sh[wid] = v;
    __syncthreads();
    float r = (threadIdx.x < (unsigned)nw) ? sh[threadIdx.x] : -INFINITY;
    if (wid == 0) {
        r = warpMax(r);
        if (lane == 0) sh[0] = r;
    }
    __syncthreads();
    r = sh[0];
    __syncthreads();
    return r;
}

__device__ __forceinline__ float gelu_exact(float x) {
    return 0.5f * x * (1.f + erff(x * 0.70710678118654752f));
}

// ---------------- 1. query = LN(phi*qg+qb)*g + b, * scale ----------------
__global__ void k_query(const float* __restrict__ phi, const float* __restrict__ qg,
                        const float* __restrict__ qb, const float* __restrict__ lg,
                        const float* __restrict__ lb, const float* __restrict__ sc) {
    int e = blockIdx.x, t = threadIdx.x;
    float y[4];
    float s = 0.f;
    #pragma unroll
    for (int i = 0; i < 4; i++) {
        int d = t + i * 256;
        y[i] = phi[e * DD + d] * qg[d] + qb[d];
        s += y[i];
    }
    float mean = blockSum(s) * (1.f / DD);
    float s2 = 0.f;
    #pragma unroll
    for (int i = 0; i < 4; i++) { float z = y[i] - mean; s2 += z * z; }
    float var = blockSum(s2) * (1.f / DD);
    float rs = rsqrtf(var + 1e-5f);
    float scale = sc[0];
    #pragma unroll
    for (int i = 0; i < 4; i++) {
        int d = t + i * 256;
        g_q[e * DD + d] = ((y[i] - mean) * rs * lg[d] + lb[d]) * scale;
    }
}

// ---------------- 2. logits[b,n,e] = sum_d (x*kg+kb)*q[e,d] ----------------
// grid 64 blocks (b, 64-row n-tile), 256 threads. smem-tiled GEMM.
__global__ void k_logits(const float* __restrict__ x, const float* __restrict__ kg,
                         const float* __restrict__ kb) {
    __shared__ float xs[64][64];
    __shared__ float qs[32][65];  // pad -> bank stride 1, conflict free for lanes e
    int t = threadIdx.x;
    int b = blockIdx.x >> 4, nb = (blockIdx.x & 15) * 64;
    int e = t & 31, ng = t >> 5;  // warp -> 8 n-rows
    float acc[8] = {0, 0, 0, 0, 0, 0, 0, 0};
    for (int dc = 0; dc < 16; dc++) {
        int dbase = dc * 64;
        #pragma unroll
        for (int k = 0; k < 16; k++) {
            int idx = t + k * 256;
            int r = idx >> 6, c = idx & 63, d = dbase + c;
            xs[r][c] = x[((b << 10) + nb + r) * DD + d] * kg[d] + kb[d];
        }
        #pragma unroll
        for (int k = 0; k < 8; k++) {
            int idx = t + k * 256;
            int r = idx >> 6, c = idx & 63;
            qs[r][c] = g_q[r * DD + dbase + c];
        }
        __syncthreads();
        #pragma unroll 4
        for (int dd = 0; dd < 64; dd++) {
            float qv = qs[e][dd];
            #pragma unroll
            for (int i = 0; i < 8; i++) acc[i] += xs[ng * 8 + i][dd] * qv;
        }
        __syncthreads();
    }
    #pragma unroll
    for (int i = 0; i < 8; i++)
        g_logits[(((b << 10) + nb + ng * 8 + i) << 5) + e] = acc[i];
}

// ---------------- 3. combine softmax (over 32 slots) + cw metric partials --
// 128 blocks x 1024 threads; one warp per (b,n) row.
__global__ void k_combine_sm() {
    int t = threadIdx.x, lane = t & 31, w = t >> 5;
    int row = blockIdx.x * 32 + w;                 // row = b*1024 + n
    float v = g_logits[(row << 5) + lane];
    float m = warpMax(v);
    float p = expf(v - m);
    float s = warpSum(p);
    float cw = p / s;
    g_combine[(row << 5) + lane] = cw;
    float s2 = warpSum(cw * cw);
    float rs = rsqrtf(s2 + 1e-9f);
    float cf = cw * rs;
    float s1 = warpSum(cf);
    int n = row & 1023;
    float c2 = (n < 32 && lane == n) ? cf * s1 : 0.f;
    c2 = warpSum(c2);
    __shared__ float p1[32], p2[32];
    if (lane == 0) { p1[w] = s1 * s1; p2[w] = c2; }
    __syncthreads();
    if (w == 0) {
        float a = warpSum(p1[lane]);
        float bb2 = warpSum(p2[lane]);
        if (lane == 0) { g_part_cw1[blockIdx.x] = a; g_part_cw2[blockIdx.x] = bb2; }
    }
}

// ---------------- 4. dispatch softmax (over N) + dw metric partials --------
// 128 blocks = (b,e) columns, 256 threads, 4 n per thread.
__global__ void k_dispatch_sm() {
    int be = blockIdx.x;
    int b = be >> 5, e = be & 31;
    int t = threadIdx.x;
    float v[4];
    float mx = -INFINITY;
    #pragma unroll
    for (int k = 0; k < 4; k++) {
        int n = t + k * 256;
        v[k] = g_logits[(((b << 10) + n) << 5) + e];
        mx = fmaxf(mx, v[k]);
    }
    mx = blockMax(mx);
    float ls = 0.f;
    #pragma unroll
    for (int k = 0; k < 4; k++) { v[k] = expf(v[k] - mx); ls += v[k]; }
    float S = blockSum(ls);
    float inv = 1.f / S;
    float s1 = 0.f, s2 = 0.f;
    #pragma unroll
    for (int k = 0; k < 4; k++) {
        int n = t + k * 256;
        float dv = v[k] * inv;
        g_dispatch[(((b << 10) + n) << 5) + e] = dv;
        s1 += dv;
        s2 += dv * dv;
    }
    float S1 = blockSum(s1);
    float S2 = blockSum(s2);
    if (t == 0) {
        float rsd = rsqrtf(S2 + 1e-9f);
        float sn = S1 * rsd;
        g_part_dw[be] = (e == 0) ? 0.f : sn * sn;  // diagonal picks (e=0,s=0)
    }
}

// ---------------- 5. slots[b,e,d] = sum_n dispatch[b,n,e]*x[b,n,d] --------
// grid (4, 16 d-tiles, 4 n-chunks), 256 threads: thread = (e-group of 8, d)
__global__ void k_slots(const float* __restrict__ x) {
    __shared__ float ws[64][32];
    int b = blockIdx.x, dt = blockIdx.y, nc = blockIdx.z;
    int t = threadIdx.x;
    int d = dt * 64 + (t & 63);
    int eb = (t >> 6) * 8;
    float acc[8] = {0, 0, 0, 0, 0, 0, 0, 0};
    for (int no = 0; no < 4; no++) {
        int nbase = nc * 256 + no * 64;
        #pragma unroll
        for (int k = 0; k < 8; k++) {
            int idx = t + k * 256;
            int r = idx >> 5, c = idx & 31;
            ws[r][c] = g_dispatch[(((b << 10) + nbase + r) << 5) + c];
        }
        __syncthreads();
        #pragma unroll 4
        for (int nn = 0; nn < 64; nn++) {
            float xv = __ldg(&x[(((b << 10) + nbase + nn) << 10) + d]);
            #pragma unroll
            for (int i = 0; i < 8; i++) acc[i] += ws[nn][eb + i] * xv;
        }
        __syncthreads();
    }
    #pragma unroll
    for (int i = 0; i < 8; i++)
        g_slots_part[nc * (BB * EE * DD) + (b * EE + eb + i) * DD + d] = acc[i];
}

__global__ void k_slots_reduce() {
    int i = blockIdx.x * 256 + threadIdx.x;
    if (i < BB * EE * DD) {
        g_slots[i] = g_slots_part[i] + g_slots_part[BB * EE * DD + i] +
                     g_slots_part[2 * BB * EE * DD + i] + g_slots_part[3 * BB * EE * DD + i];
    }
}

// ---------------- 6. h = gelu(slots @ w1 + b1)  (reads 512 MB w1 once) ----
// grid (32 experts, 16 j-tiles of 256), 128 threads, float2 per thread.
__global__ void k_mlp1(const float* __restrict__ w1, const float* __restrict__ b1) {
    __shared__ float ss[4][1024];
    int e = blockIdx.x, jt = blockIdx.y, t = threadIdx.x;
    #pragma unroll
    for (int k = 0; k < 32; k++) {
        int idx = t + k * 128;
        int b = idx >> 10, d = idx & 1023;
        ss[b][d] = g_slots[(b * EE + e) * DD + d];
    }
    __syncthreads();
    int j0 = jt * 256 + t * 2;
    const float2* wp = (const float2*)(w1 + (size_t)e * DD * HHH + j0);
    float a0x = 0, a0y = 0, a1x = 0, a1y = 0, a2x = 0, a2y = 0, a3x = 0, a3y = 0;
    #pragma unroll 8
    for (int d = 0; d < 1024; d++) {
        float2 w = __ldg(&wp[(size_t)d * (HHH / 2)]);
        float s0 = ss[0][d], s1 = ss[1][d], s2 = ss[2][d], s3 = ss[3][d];
        a0x += s0 * w.x; a0y += s0 * w.y;
        a1x += s1 * w.x; a1y += s1 * w.y;
        a2x += s2 * w.x; a2y += s2 * w.y;
        a3x += s3 * w.x; a3y += s3 * w.y;
    }
    float bx = b1[e * HHH + j0], by = b1[e * HHH + j0 + 1];
    g_h[(0 * EE + e) * HHH + j0]     = gelu_exact(a0x + bx);
    g_h[(0 * EE + e) * HHH + j0 + 1] = gelu_exact(a0y + by);
    g_h[(1 * EE + e) * HHH + j0]     = gelu_exact(a1x + bx);
    g_h[(1 * EE + e) * HHH + j0 + 1] = gelu_exact(a1y + by);
    g_h[(2 * EE + e) * HHH + j0]     = gelu_exact(a2x + bx);
    g_h[(2 * EE + e) * HHH + j0 + 1] = gelu_exact(a2y + by);
    g_h[(3 * EE + e) * HHH + j0]     = gelu_exact(a3x + bx);
    g_h[(3 * EE + e) * HHH + j0 + 1] = gelu_exact(a3y + by);
}

// ---------------- 7. expert_out = h @ w2 (+ b2)  (reads 512 MB w2 once) ---
// grid (32 experts, 8 d-tiles of 128, 2 h-halves), 128 threads.
__global__ void k_mlp2(const float* __restrict__ w2) {
    __shared__ float hs[4][512];
    int e = blockIdx.x, dt = blockIdx.y, hf = blockIdx.z, t = threadIdx.x;
    int d = dt * 128 + t;
    int hbase = hf * 2048;
    float acc[4] = {0, 0, 0, 0};
    for (int hc = 0; hc < 4; hc++) {
        #pragma unroll
        for (int k = 0; k < 16; k++) {
            int idx = t + k * 128;
            int b = idx >> 9, hh = idx & 511;
            hs[b][hh] = g_h[(b * EE + e) * HHH + hbase + hc * 512 + hh];
        }
        __syncthreads();
        const float* wp = w2 + ((size_t)e * HHH + hbase + hc * 512) * DD + d;
        #pragma unroll 8
        for (int hh = 0; hh < 512; hh++) {
            float w = __ldg(wp + (size_t)hh * DD);
            acc[0] += hs[0][hh] * w;
            acc[1] += hs[1][hh] * w;
            acc[2] += hs[2][hh] * w;
            acc[3] += hs[3][hh] * w;
        }
        __syncthreads();
    }
    #pragma unroll
    for (int b = 0; b < 4; b++)
        g_eout_part[hf * (BB * EE * DD) + (b * EE + e) * DD + d] = acc[b];
}

__global__ void k_mlp2_reduce(const float* __restrict__ b2) {
    int i = blockIdx.x * 256 + threadIdx.x;
    if (i < BB * EE * DD) {
        int e = (i >> 10) & 31, d = i & 1023;
        g_eout[i] = g_eout_part[i] + g_eout_part[BB * EE * DD + i] + b2[e * DD + d];
    }
}

// ---------------- 8. out[b,n,d] = sum_e combine[b,n,e]*eout[b,e,d] --------
// grid (4, 16 n-tiles of 64, 4 d-tiles of 256), 256 threads.
__global__ void k_out(float* __restrict__ out) {
    __shared__ float eo[32][256];
    __shared__ float cw[64][32];
    int b = blockIdx.x, nt = blockIdx.y, dt = blockIdx.z, t = threadIdx.x;
    #pragma unroll
    for (int k = 0; k < 32; k++) {
        int idx = t + k * 256;
        int e = idx >> 8, c = idx & 255;
        eo[e][c] = g_eout[(b * EE + e) * DD + dt * 256 + c];
    }
    #pragma unroll
    for (int k = 0; k < 8; k++) {
        int idx = t + k * 256;
        int r = idx >> 5, c = idx & 31;
        cw[r][c] = g_combine[(((b << 10) + nt * 64 + r) << 5) + c];
    }
    __syncthreads();
    int d = dt * 256 + t;
    for (int n = 0; n < 64; n++) {
        float a = 0.f;
        #pragma unroll
        for (int e = 0; e < 32; e++) a += cw[n][e] * eo[e][t];
        out[(((b << 10) + nt * 64 + n) << 10) + d] = a;
    }
}

// ---------------- 9. metrics finalization (deterministic) -----------------
__global__ void k_final(float* __restrict__ out, int out_size) {
    int t = threadIdx.x;  // 128 threads
    float a = g_part_cw1[t];
    float b = g_part_cw2[t];
    float c = g_part_dw[t];
    a = blockSum(a);
    b = blockSum(b);
    c = blockSum(c);
    if (t == 0) {
        out[out_size - 2] = (a - b) / (float)(4.0 * 1024.0 * 1023.0);
        out[out_size - 1] = c / (float)(4 * 32 * 31);
    }
}

// ---------------- launch ----------------
extern "C" void kernel_launch(void* const* d_in, const int* in_sizes, int n_in,
                              void* d_out, int out_size) {
    const float* x   = (const float*)d_in[0];
    const float* phi = (const float*)d_in[1];
    const float* kg  = (const float*)d_in[2];
    const float* kb  = (const float*)d_in[3];
    const float* qg  = (const float*)d_in[4];
    const float* qb  = (const float*)d_in[5];
    const float* lg  = (const float*)d_in[6];
    const float* lb  = (const float*)d_in[7];
    const float* sc  = (const float*)d_in[8];
    const float* w1  = (const float*)d_in[9];
    const float* b1  = (const float*)d_in[10];
    const float* w2  = (const float*)d_in[11];
    const float* b2  = (const float*)d_in[12];
    float* out = (float*)d_out;

    k_query<<<32, 256>>>(phi, qg, qb, lg, lb, sc);
    k_logits<<<64, 256>>>(x, kg, kb);
    k_combine_sm<<<128, 1024>>>();
    k_dispatch_sm<<<128, 256>>>();
    k_slots<<<dim3(4, 16, 4), 256>>>(x);
    k_slots_reduce<<<512, 256>>>();
    k_mlp1<<<dim3(32, 16), 128>>>(w1, b1);
    k_mlp2<<<dim3(32, 8, 2), 128>>>(w2);
    k_mlp2_reduce<<<512, 256>>>(b2);
    k_out<<<dim3(4, 16, 4), 256>>>(out);
    k_final<<<1, 128>>>(out, out_size);
}

// round 2
// speedup vs baseline: 2.6178x; 2.6178x over previous
#include <cuda_runtime.h>
#include <math.h>

#define BB 4
#define NN 1024
#define DD 1024
#define EE 32
#define HHH 4096

// ---------------- scratch (device globals; no allocation allowed) ----------
__device__ float g_q[EE * DD];                     // 128 KB
__device__ float g_logits[BB * NN * EE];           // 512 KB
__device__ float g_combine[BB * NN * EE];          // 512 KB
__device__ float g_dispatch[BB * NN * EE];         // 512 KB
__device__ float g_slots_part[4 * BB * EE * DD];   // 2 MB
__device__ float g_slots[BB * EE * DD];            // 512 KB
__device__ float g_h_part[4 * BB * EE * HHH];      // 8 MB
__device__ float g_h[BB * EE * HHH];               // 2 MB
__device__ float g_eout_part[16 * BB * EE * DD];   // 8 MB
__device__ float g_eout[BB * EE * DD];             // 512 KB
__device__ float g_part_cw1[128];
__device__ float g_part_cw2[128];
__device__ float g_part_dw[128];

// ---------------- reduction helpers ----------------
__device__ __forceinline__ float warpSum(float v) {
    #pragma unroll
    for (int o = 16; o; o >>= 1) v += __shfl_xor_sync(0xffffffffu, v, o);
    return v;
}
__device__ __forceinline__ float warpMax(float v) {
    #pragma unroll
    for (int o = 16; o; o >>= 1) v = fmaxf(v, __shfl_xor_sync(0xffffffffu, v, o));
    return v;
}
__device__ float blockSum(float v) {
    __shared__ float sh[32];
    int lane = threadIdx.x & 31, wid = threadIdx.x >> 5;
    int nw = (blockDim.x + 31) >> 5;
    v = warpSum(v);
    if (lane == 0) sh[wid] = v;
    __syncthreads();
    float r = (threadIdx.x < (unsigned)nw) ? sh[threadIdx.x] : 0.f;
    if (wid == 0) {
        r = warpSum(r);
        if (lane == 0) sh[0] = r;
    }
    __syncthreads();
    r = sh[0];
    __syncthreads();
    return r;
}
__device__ float blockMax(float v) {
    __shared__ float sh[32];
    int lane = threadIdx.x & 31, wid = threadIdx.x >> 5;
    int nw = (blockDim.x + 31) >> 5;
    v = warpMax(v);
    if (lane == 0) sh[wid] = v;
    __syncthreads();
    float r = (threadIdx.x < (unsigned)nw) ? sh[threadIdx.x] : -INFINITY;
    if (wid == 0) {
        r = warpMax(r);
        if (lane == 0) sh[0] = r;
    }
    __syncthreads();
    r = sh[0];
    __syncthreads();
    return r;
}

__device__ __forceinline__ float gelu_exact(float x) {
    return 0.5f * x * (1.f + erff(x * 0.70710678118654752f));
}

// ---------------- 1. query = LN(phi*qg+qb)*g + b, * scale ----------------
__global__ void k_query(const float* __restrict__ phi, const float* __restrict__ qg,
                        const float* __restrict__ qb, const float* __restrict__ lg,
                        const float* __restrict__ lb, const float* __restrict__ sc) {
    int e = blockIdx.x, t = threadIdx.x;
    float y[4];
    float s = 0.f;
    #pragma unroll
    for (int i = 0; i < 4; i++) {
        int d = t + i * 256;
        y[i] = phi[e * DD + d] * qg[d] + qb[d];
        s += y[i];
    }
    float mean = blockSum(s) * (1.f / DD);
    float s2 = 0.f;
    #pragma unroll
    for (int i = 0; i < 4; i++) { float z = y[i] - mean; s2 += z * z; }
    float var = blockSum(s2) * (1.f / DD);
    float rs = rsqrtf(var + 1e-5f);
    float scale = sc[0];
    #pragma unroll
    for (int i = 0; i < 4; i++) {
        int d = t + i * 256;
        g_q[e * DD + d] = ((y[i] - mean) * rs * lg[d] + lb[d]) * scale;
    }
}

// ---------------- 2. logits[b,n,e] = sum_d (x*kg+kb)*q[e,d] ----------------
__global__ void k_logits(const float* __restrict__ x, const float* __restrict__ kg,
                         const float* __restrict__ kb) {
    __shared__ float xs[64][64];
    __shared__ float qs[32][65];
    int t = threadIdx.x;
    int b = blockIdx.x >> 4, nb = (blockIdx.x & 15) * 64;
    int e = t & 31, ng = t >> 5;
    float acc[8] = {0, 0, 0, 0, 0, 0, 0, 0};
    for (int dc = 0; dc < 16; dc++) {
        int dbase = dc * 64;
        #pragma unroll
        for (int k = 0; k < 16; k++) {
            int idx = t + k * 256;
            int r = idx >> 6, c = idx & 63, d = dbase + c;
            xs[r][c] = x[((b << 10) + nb + r) * DD + d] * kg[d] + kb[d];
        }
        #pragma unroll
        for (int k = 0; k < 8; k++) {
            int idx = t + k * 256;
            int r = idx >> 6, c = idx & 63;
            qs[r][c] = g_q[r * DD + dbase + c];
        }
        __syncthreads();
        #pragma unroll 4
        for (int dd = 0; dd < 64; dd++) {
            float qv = qs[e][dd];
            #pragma unroll
            for (int i = 0; i < 8; i++) acc[i] += xs[ng * 8 + i][dd] * qv;
        }
        __syncthreads();
    }
    #pragma unroll
    for (int i = 0; i < 8; i++)
        g_logits[(((b << 10) + nb + ng * 8 + i) << 5) + e] = acc[i];
}

// ---------------- 3. combine softmax + cw metric partials --
__global__ void k_combine_sm() {
    int t = threadIdx.x, lane = t & 31, w = t >> 5;
    int row = blockIdx.x * 32 + w;
    float v = g_logits[(row << 5) + lane];
    float m = warpMax(v);
    float p = expf(v - m);
    float s = warpSum(p);
    float cw = p / s;
    g_combine[(row << 5) + lane] = cw;
    float s2 = warpSum(cw * cw);
    float rs = rsqrtf(s2 + 1e-9f);
    float cf = cw * rs;
    float s1 = warpSum(cf);
    int n = row & 1023;
    float c2 = (n < 32 && lane == n) ? cf * s1 : 0.f;
    c2 = warpSum(c2);
    __shared__ float p1[32], p2[32];
    if (lane == 0) { p1[w] = s1 * s1; p2[w] = c2; }
    __syncthreads();
    if (w == 0) {
        float a = warpSum(p1[lane]);
        float bb2 = warpSum(p2[lane]);
        if (lane == 0) { g_part_cw1[blockIdx.x] = a; g_part_cw2[blockIdx.x] = bb2; }
    }
}

// ---------------- 4. dispatch softmax + dw metric partials --------
__global__ void k_dispatch_sm() {
    int be = blockIdx.x;
    int b = be >> 5, e = be & 31;
    int t = threadIdx.x;
    float v[4];
    float mx = -INFINITY;
    #pragma unroll
    for (int k = 0; k < 4; k++) {
        int n = t + k * 256;
        v[k] = g_logits[(((b << 10) + n) << 5) + e];
        mx = fmaxf(mx, v[k]);
    }
    mx = blockMax(mx);
    float ls = 0.f;
    #pragma unroll
    for (int k = 0; k < 4; k++) { v[k] = expf(v[k] - mx); ls += v[k]; }
    float S = blockSum(ls);
    float inv = 1.f / S;
    float s1 = 0.f, s2 = 0.f;
    #pragma unroll
    for (int k = 0; k < 4; k++) {
        int n = t + k * 256;
        float dv = v[k] * inv;
        g_dispatch[(((b << 10) + n) << 5) + e] = dv;
        s1 += dv;
        s2 += dv * dv;
    }
    float S1 = blockSum(s1);
    float S2 = blockSum(s2);
    if (t == 0) {
        float rsd = rsqrtf(S2 + 1e-9f);
        float sn = S1 * rsd;
        g_part_dw[be] = (e == 0) ? 0.f : sn * sn;
    }
}

// ---------------- 5. slots[b,e,d] = sum_n dispatch[b,n,e]*x[b,n,d] --------
__global__ void k_slots(const float* __restrict__ x) {
    __shared__ float ws[64][32];
    int b = blockIdx.x, dt = blockIdx.y, nc = blockIdx.z;
    int t = threadIdx.x;
    int d = dt * 64 + (t & 63);
    int eb = (t >> 6) * 8;
    float acc[8] = {0, 0, 0, 0, 0, 0, 0, 0};
    for (int no = 0; no < 4; no++) {
        int nbase = nc * 256 + no * 64;
        #pragma unroll
        for (int k = 0; k < 8; k++) {
            int idx = t + k * 256;
            int r = idx >> 5, c = idx & 31;
            ws[r][c] = g_dispatch[(((b << 10) + nbase + r) << 5) + c];
        }
        __syncthreads();
        #pragma unroll 4
        for (int nn = 0; nn < 64; nn++) {
            float xv = __ldg(&x[(((b << 10) + nbase + nn) << 10) + d]);
            #pragma unroll
            for (int i = 0; i < 8; i++) acc[i] += ws[nn][eb + i] * xv;
        }
        __syncthreads();
    }
    #pragma unroll
    for (int i = 0; i < 8; i++)
        g_slots_part[nc * (BB * EE * DD) + (b * EE + eb + i) * DD + d] = acc[i];
}

__global__ void k_slots_reduce() {
    int i = blockIdx.x * 256 + threadIdx.x;
    if (i < BB * EE * DD) {
        g_slots[i] = g_slots_part[i] + g_slots_part[BB * EE * DD + i] +
                     g_slots_part[2 * BB * EE * DD + i] + g_slots_part[3 * BB * EE * DD + i];
    }
}

// ---------------- 6. MLP1 partial: grid (32 e, 4 jt, 4 dc), 256 thr --------
// h_part[dc][b,e,j] = sum_{d in chunk dc} slots[b,e,d] * w1[e,d,j]
__global__ void k_mlp1(const float* __restrict__ w1) {
    __shared__ float ss[4][256];
    int e = blockIdx.x, jt = blockIdx.y, dc = blockIdx.z, t = threadIdx.x;
    #pragma unroll
    for (int k = 0; k < 4; k++) {
        int idx = t + k * 256;
        int b = idx >> 8, d = idx & 255;
        ss[b][d] = g_slots[(b * EE + e) * DD + dc * 256 + d];
    }
    __syncthreads();
    int j0 = jt * 1024 + t * 4;
    const float4* wp = (const float4*)(w1 + (size_t)e * DD * HHH + (size_t)(dc * 256) * HHH + j0);
    float4 a0 = {0,0,0,0}, a1 = {0,0,0,0}, a2 = {0,0,0,0}, a3 = {0,0,0,0};
    #pragma unroll 8
    for (int d = 0; d < 256; d++) {
        float4 w = __ldg(&wp[(size_t)d * (HHH / 4)]);
        float s0 = ss[0][d], s1 = ss[1][d], s2 = ss[2][d], s3 = ss[3][d];
        a0.x += s0 * w.x; a0.y += s0 * w.y; a0.z += s0 * w.z; a0.w += s0 * w.w;
        a1.x += s1 * w.x; a1.y += s1 * w.y; a1.z += s1 * w.z; a1.w += s1 * w.w;
        a2.x += s2 * w.x; a2.y += s2 * w.y; a2.z += s2 * w.z; a2.w += s2 * w.w;
        a3.x += s3 * w.x; a3.y += s3 * w.y; a3.z += s3 * w.z; a3.w += s3 * w.w;
    }
    float4* op = (float4*)(g_h_part + (size_t)dc * (BB * EE * HHH));
    op[((0 * EE + e) * HHH + j0) >> 2] = a0;
    op[((1 * EE + e) * HHH + j0) >> 2] = a1;
    op[((2 * EE + e) * HHH + j0) >> 2] = a2;
    op[((3 * EE + e) * HHH + j0) >> 2] = a3;
}

// ---------------- 6b. h = gelu(sum_dc h_part + b1) -------------------------
__global__ void k_h_reduce(const float* __restrict__ b1) {
    int i4 = blockIdx.x * 256 + threadIdx.x;   // 131072 float4s
    const float4* p0 = (const float4*)g_h_part;
    const float4* p1 = (const float4*)(g_h_part + BB * EE * HHH);
    const float4* p2 = (const float4*)(g_h_part + 2 * BB * EE * HHH);
    const float4* p3 = (const float4*)(g_h_part + 3 * BB * EE * HHH);
    float4 v0 = p0[i4], v1 = p1[i4], v2 = p2[i4], v3 = p3[i4];
    int i = i4 << 2;
    int e = (i >> 12) & 31, j = i & (HHH - 1);
    float4 bb = *(const float4*)(b1 + e * HHH + j);
    float4 r;
    r.x = gelu_exact(v0.x + v1.x + v2.x + v3.x + bb.x);
    r.y = gelu_exact(v0.y + v1.y + v2.y + v3.y + bb.y);
    r.z = gelu_exact(v0.z + v1.z + v2.z + v3.z + bb.z);
    r.w = gelu_exact(v0.w + v1.w + v2.w + v3.w + bb.w);
    ((float4*)g_h)[i4] = r;
}

// ---------------- 7. MLP2 partial: grid (32 e, 16 hc), 256 thr -------------
// eout_part[hc][b,e,d] = sum_{h in chunk hc} h[b,e,h] * w2[e,h,d]
__global__ void k_mlp2(const float* __restrict__ w2) {
    __shared__ float hs[4][256];
    int e = blockIdx.x, hc = blockIdx.y, t = threadIdx.x;
    #pragma unroll
    for (int k = 0; k < 4; k++) {
        int idx = t + k * 256;
        int b = idx >> 8, hh = idx & 255;
        hs[b][hh] = g_h[(b * EE + e) * HHH + hc * 256 + hh];
    }
    __syncthreads();
    int d0 = t * 4;
    const float4* wp = (const float4*)(w2 + ((size_t)e * HHH + hc * 256) * DD + d0);
    float4 a0 = {0,0,0,0}, a1 = {0,0,0,0}, a2 = {0,0,0,0}, a3 = {0,0,0,0};
    #pragma unroll 8
    for (int hh = 0; hh < 256; hh++) {
        float4 w = __ldg(&wp[(size_t)hh * (DD / 4)]);
        float h0 = hs[0][hh], h1 = hs[1][hh], h2 = hs[2][hh], h3 = hs[3][hh];
        a0.x += h0 * w.x; a0.y += h0 * w.y; a0.z += h0 * w.z; a0.w += h0 * w.w;
        a1.x += h1 * w.x; a1.y += h1 * w.y; a1.z += h1 * w.z; a1.w += h1 * w.w;
        a2.x += h2 * w.x; a2.y += h2 * w.y; a2.z += h2 * w.z; a2.w += h2 * w.w;
        a3.x += h3 * w.x; a3.y += h3 * w.y; a3.z += h3 * w.z; a3.w += h3 * w.w;
    }
    float4* op = (float4*)(g_eout_part + (size_t)hc * (BB * EE * DD));
    op[((0 * EE + e) * DD + d0) >> 2] = a0;
    op[((1 * EE + e) * DD + d0) >> 2] = a1;
    op[((2 * EE + e) * DD + d0) >> 2] = a2;
    op[((3 * EE + e) * DD + d0) >> 2] = a3;
}

// ---------------- 7b. eout = sum_hc eout_part + b2 --------------------------
__global__ void k_eout_reduce(const float* __restrict__ b2) {
    int i4 = blockIdx.x * 256 + threadIdx.x;   // 32768 float4s
    float4 acc = {0, 0, 0, 0};
    #pragma unroll
    for (int c = 0; c < 16; c++) {
        float4 v = ((const float4*)(g_eout_part + (size_t)c * (BB * EE * DD)))[i4];
        acc.x += v.x; acc.y += v.y; acc.z += v.z; acc.w += v.w;
    }
    int i = i4 << 2;
    int e = (i >> 10) & 31, d = i & 1023;
    float4 bb = *(const float4*)(b2 + e * DD + d);
    acc.x += bb.x; acc.y += bb.y; acc.z += bb.z; acc.w += bb.w;
    ((float4*)g_eout)[i4] = acc;
}

// ---------------- 8. out[b,n,d] = sum_e combine[b,n,e]*eout[b,e,d] --------
__global__ void k_out(float* __restrict__ out) {
    __shared__ float eo[32][256];
    __shared__ float cw[64][32];
    int b = blockIdx.x, nt = blockIdx.y, dt = blockIdx.z, t = threadIdx.x;
    #pragma unroll
    for (int k = 0; k < 32; k++) {
        int idx = t + k * 256;
        int e = idx >> 8, c = idx & 255;
        eo[e][c] = g_eout[(b * EE + e) * DD + dt * 256 + c];
    }
    #pragma unroll
    for (int k = 0; k < 8; k++) {
        int idx = t + k * 256;
        int r = idx >> 5, c = idx & 31;
        cw[r][c] = g_combine[(((b << 10) + nt * 64 + r) << 5) + c];
    }
    __syncthreads();
    int d = dt * 256 + t;
    for (int n = 0; n < 64; n++) {
        float a = 0.f;
        #pragma unroll
        for (int e = 0; e < 32; e++) a += cw[n][e] * eo[e][t];
        out[(((b << 10) + nt * 64 + n) << 10) + d] = a;
    }
}

// ---------------- 9. metrics finalization -----------------
__global__ void k_final(float* __restrict__ out, int out_size) {
    int t = threadIdx.x;
    float a = g_part_cw1[t];
    float b = g_part_cw2[t];
    float c = g_part_dw[t];
    a = blockSum(a);
    b = blockSum(b);
    c = blockSum(c);
    if (t == 0) {
        out[out_size - 2] = (a - b) / (float)(4.0 * 1024.0 * 1023.0);
        out[out_size - 1] = c / (float)(4 * 32 * 31);
    }
}

// ---------------- launch ----------------
extern "C" void kernel_launch(void* const* d_in, const int* in_sizes, int n_in,
                              void* d_out, int out_size) {
    const float* x   = (const float*)d_in[0];
    const float* phi = (const float*)d_in[1];
    const float* kg  = (const float*)d_in[2];
    const float* kb  = (const float*)d_in[3];
    const float* qg  = (const float*)d_in[4];
    const float* qb  = (const float*)d_in[5];
    const float* lg  = (const float*)d_in[6];
    const float* lb  = (const float*)d_in[7];
    const float* sc  = (const float*)d_in[8];
    const float* w1  = (const float*)d_in[9];
    const float* b1  = (const float*)d_in[10];
    const float* w2  = (const float*)d_in[11];
    const float* b2  = (const float*)d_in[12];
    float* out = (float*)d_out;

    k_query<<<32, 256>>>(phi, qg, qb, lg, lb, sc);
    k_logits<<<64, 256>>>(x, kg, kb);
    k_combine_sm<<<128, 1024>>>();
    k_dispatch_sm<<<128, 256>>>();
    k_slots<<<dim3(4, 16, 4), 256>>>(x);
    k_slots_reduce<<<512, 256>>>();
    k_mlp1<<<dim3(32, 4, 4), 256>>>(w1);
    k_h_reduce<<<512, 256>>>(b1);
    k_mlp2<<<dim3(32, 16), 256>>>(w2);
    k_eout_reduce<<<128, 256>>>(b2);
    k_out<<<dim3(4, 16, 4), 256>>>(out);
    k_final<<<1, 128>>>(out, out_size);
}

// round 5
// speedup vs baseline: 2.7133x; 1.0365x over previous
#include <cuda_runtime.h>
#include <math.h>

#define BB 4
#define NN 1024
#define DD 1024
#define EE 32
#define HHH 4096

// ---------------- scratch (device globals; no allocation allowed) ----------
__device__ float g_q[EE * DD];                      // 128 KB
__device__ float g_logits[BB * NN * EE];            // 512 KB  [b,n,e]
__device__ float g_logitsT[BB * EE * NN];           // 512 KB  [b,e,n]
__device__ float g_combine[BB * NN * EE];           // 512 KB  [b,n,e]
__device__ float g_dispT[BB * EE * NN];             // 512 KB  [b,e,n]
__device__ float g_slots_part[4 * BB * EE * DD];    // 2 MB
__device__ float g_h_part[8 * BB * EE * HHH];       // 16 MB
__device__ float g_eout_part[32 * BB * EE * DD];    // 16 MB
__device__ float g_eout[BB * EE * DD];              // 512 KB
__device__ float g_part_cw1[128];
__device__ float g_part_cw2[128];
__device__ float g_part_dw[128];

// ---------------- reduction helpers ----------------
__device__ __forceinline__ float warpSum(float v) {
    #pragma unroll
    for (int o = 16; o; o >>= 1) v += __shfl_xor_sync(0xffffffffu, v, o);
    return v;
}
__device__ __forceinline__ float warpMax(float v) {
    #pragma unroll
    for (int o = 16; o; o >>= 1) v = fmaxf(v, __shfl_xor_sync(0xffffffffu, v, o));
    return v;
}
__device__ float blockSum(float v) {
    __shared__ float sh[32];
    int lane = threadIdx.x & 31, wid = threadIdx.x >> 5;
    int nw = (blockDim.x + 31) >> 5;
    v = warpSum(v);
    if (lane == 0) sh[wid] = v;
    __syncthreads();
    float r = (threadIdx.x < (unsigned)nw) ? sh[threadIdx.x] : 0.f;
    if (wid == 0) {
        r = warpSum(r);
        if (lane == 0) sh[0] = r;
    }
    __syncthreads();
    r = sh[0];
    __syncthreads();
    return r;
}
__device__ float blockMax(float v) {
    __shared__ float sh[32];
    int lane = threadIdx.x & 31, wid = threadIdx.x >> 5;
    int nw = (blockDim.x + 31) >> 5;
    v = warpMax(v);
    if (lane == 0) sh[wid] = v;
    __syncthreads();
    float r = (threadIdx.x < (unsigned)nw) ? sh[threadIdx.x] : -INFINITY;
    if (wid == 0) {
        r = warpMax(r);
        if (lane == 0) sh[0] = r;
    }
    __syncthreads();
    r = sh[0];
    __syncthreads();
    return r;
}

__device__ __forceinline__ float gelu_exact(float x) {
    return 0.5f * x * (1.f + erff(x * 0.70710678118654752f));
}

// ---------------- 1. query = LN(phi*qg+qb)*g + b, * scale ----------------
__global__ void k_query(const float* __restrict__ phi, const float* __restrict__ qg,
                        const float* __restrict__ qb, const float* __restrict__ lg,
                        const float* __restrict__ lb, const float* __restrict__ sc) {
    int e = blockIdx.x, t = threadIdx.x;
    float y[4];
    float s = 0.f;
    #pragma unroll
    for (int i = 0; i < 4; i++) {
        int d = t + i * 256;
        y[i] = phi[e * DD + d] * qg[d] + qb[d];
        s += y[i];
    }
    float mean = blockSum(s) * (1.f / DD);
    float s2 = 0.f;
    #pragma unroll
    for (int i = 0; i < 4; i++) { float z = y[i] - mean; s2 += z * z; }
    float var = blockSum(s2) * (1.f / DD);
    float rs = rsqrtf(var + 1e-5f);
    float scale = sc[0];
    #pragma unroll
    for (int i = 0; i < 4; i++) {
        int d = t + i * 256;
        g_q[e * DD + d] = ((y[i] - mean) * rs * lg[d] + lb[d]) * scale;
    }
}

// ---------------- 2. logits[b,n,e] = sum_d (x*kg+kb)*q[e,d]; also write T --
__global__ void k_logits(const float* __restrict__ x, const float* __restrict__ kg,
                         const float* __restrict__ kb) {
    __shared__ float xs[64][64];
    __shared__ float qs[32][65];
    __shared__ float ts[64][33];
    int t = threadIdx.x;
    int b = blockIdx.x >> 4, nb = (blockIdx.x & 15) * 64;
    int e = t & 31, ng = t >> 5;
    float acc[8] = {0, 0, 0, 0, 0, 0, 0, 0};
    for (int dc = 0; dc < 16; dc++) {
        int dbase = dc * 64;
        #pragma unroll
        for (int k = 0; k < 16; k++) {
            int idx = t + k * 256;
            int r = idx >> 6, c = idx & 63, d = dbase + c;
            xs[r][c] = x[((b << 10) + nb + r) * DD + d] * kg[d] + kb[d];
        }
        #pragma unroll
        for (int k = 0; k < 8; k++) {
            int idx = t + k * 256;
            int r = idx >> 6, c = idx & 63;
            qs[r][c] = g_q[r * DD + dbase + c];
        }
        __syncthreads();
        #pragma unroll 4
        for (int dd = 0; dd < 64; dd++) {
            float qv = qs[e][dd];
            #pragma unroll
            for (int i = 0; i < 8; i++) acc[i] += xs[ng * 8 + i][dd] * qv;
        }
        __syncthreads();
    }
    #pragma unroll
    for (int i = 0; i < 8; i++) {
        g_logits[(((b << 10) + nb + ng * 8 + i) << 5) + e] = acc[i];
        ts[ng * 8 + i][e] = acc[i];
    }
    __syncthreads();
    #pragma unroll
    for (int k = 0; k < 8; k++) {
        int idx = t + k * 256;
        int ee = idx >> 6, n = idx & 63;
        g_logitsT[(((b << 5) + ee) << 10) + nb + n] = ts[n][ee];
    }
}

// ---------------- 3. combine softmax + cw metric partials --
__global__ void k_combine_sm() {
    int t = threadIdx.x, lane = t & 31, w = t >> 5;
    int row = blockIdx.x * 32 + w;
    float v = g_logits[(row << 5) + lane];
    float m = warpMax(v);
    float p = expf(v - m);
    float s = warpSum(p);
    float cw = p / s;
    g_combine[(row << 5) + lane] = cw;
    float s2 = warpSum(cw * cw);
    float rs = rsqrtf(s2 + 1e-9f);
    float cf = cw * rs;
    float s1 = warpSum(cf);
    int n = row & 1023;
    float c2 = (n < 32 && lane == n) ? cf * s1 : 0.f;
    c2 = warpSum(c2);
    __shared__ float p1[32], p2[32];
    if (lane == 0) { p1[w] = s1 * s1; p2[w] = c2; }
    __syncthreads();
    if (w == 0) {
        float a = warpSum(p1[lane]);
        float bb2 = warpSum(p2[lane]);
        if (lane == 0) { g_part_cw1[blockIdx.x] = a; g_part_cw2[blockIdx.x] = bb2; }
    }
}

// ---------------- 4. dispatch softmax over N (coalesced via T layout) ------
__global__ void k_dispatch_sm() {
    int be = blockIdx.x;          // be = b*32 + e
    int e = be & 31;
    int t = threadIdx.x;
    float v[4];
    float mx = -INFINITY;
    #pragma unroll
    for (int k = 0; k < 4; k++) {
        int n = t + k * 256;
        v[k] = g_logitsT[(be << 10) + n];
        mx = fmaxf(mx, v[k]);
    }
    mx = blockMax(mx);
    float ls = 0.f;
    #pragma unroll
    for (int k = 0; k < 4; k++) { v[k] = expf(v[k] - mx); ls += v[k]; }
    float S = blockSum(ls);
    float inv = 1.f / S;
    float s1 = 0.f, s2 = 0.f;
    #pragma unroll
    for (int k = 0; k < 4; k++) {
        int n = t + k * 256;
        float dv = v[k] * inv;
        g_dispT[(be << 10) + n] = dv;
        s1 += dv;
        s2 += dv * dv;
    }
    float S1 = blockSum(s1);
    float S2 = blockSum(s2);
    if (t == 0) {
        float rsd = rsqrtf(S2 + 1e-9f);
        float sn = S1 * rsd;
        g_part_dw[be] = (e == 0) ? 0.f : sn * sn;
    }
}

// ---------------- 5. slots[b,e,d] = sum_n dispT[b,e,n]*x[b,n,d] -----------
__global__ void k_slots(const float* __restrict__ x) {
    __shared__ float ws[64][33];
    int b = blockIdx.x, dt = blockIdx.y, nc = blockIdx.z;
    int t = threadIdx.x;
    int d = dt * 64 + (t & 63);
    int eb = (t >> 6) * 8;
    float acc[8] = {0, 0, 0, 0, 0, 0, 0, 0};
    for (int no = 0; no < 4; no++) {
        int nbase = nc * 256 + no * 64;
        #pragma unroll
        for (int k = 0; k < 8; k++) {
            int idx = t + k * 256;            // 2048 = 32e * 64n
            int ee = idx >> 6, n = idx & 63;
            ws[n][ee] = g_dispT[(((b << 5) + ee) << 10) + nbase + n];
        }
        __syncthreads();
        #pragma unroll 4
        for (int nn = 0; nn < 64; nn++) {
            float xv = __ldg(&x[(((b << 10) + nbase + nn) << 10) + d]);
            #pragma unroll
            for (int i = 0; i < 8; i++) acc[i] += ws[nn][eb + i] * xv;
        }
        __syncthreads();
    }
    #pragma unroll
    for (int i = 0; i < 8; i++)
        g_slots_part[nc * (BB * EE * DD) + (b * EE + eb + i) * DD + d] = acc[i];
}

// ---------------- 6. MLP1 partial: grid (32 e, 4 jt, 8 dc), 256 thr --------
// (slots nc-reduce fused into prologue)
__global__ void k_mlp1(const float* __restrict__ w1) {
    __shared__ float ss[4][128];
    int e = blockIdx.x, jt = blockIdx.y, dc = blockIdx.z, t = threadIdx.x;
    #pragma unroll
    for (int k = 0; k < 2; k++) {
        int idx = t + k * 256;
        int b = idx >> 7, d = idx & 127;
        float s = 0.f;
        #pragma unroll
        for (int nc = 0; nc < 4; nc++)
            s += g_slots_part[nc * (BB * EE * DD) + (b * EE + e) * DD + dc * 128 + d];
        ss[b][d] = s;
    }
    __syncthreads();
    int j0 = jt * 1024 + t * 4;
    const float4* wp = (const float4*)(w1 + ((size_t)e * DD + dc * 128) * HHH + j0);
    float4 a0 = {0,0,0,0}, a1 = {0,0,0,0}, a2 = {0,0,0,0}, a3 = {0,0,0,0};
    #pragma unroll 16
    for (int d = 0; d < 128; d++) {
        float4 w = __ldcs(&wp[(size_t)d * (HHH / 4)]);
        float s0 = ss[0][d], s1 = ss[1][d], s2 = ss[2][d], s3 = ss[3][d];
        a0.x += s0 * w.x; a0.y += s0 * w.y; a0.z += s0 * w.z; a0.w += s0 * w.w;
        a1.x += s1 * w.x; a1.y += s1 * w.y; a1.z += s1 * w.z; a1.w += s1 * w.w;
        a2.x += s2 * w.x; a2.y += s2 * w.y; a2.z += s2 * w.z; a2.w += s2 * w.w;
        a3.x += s3 * w.x; a3.y += s3 * w.y; a3.z += s3 * w.z; a3.w += s3 * w.w;
    }
    float4* op = (float4*)(g_h_part + (size_t)dc * (BB * EE * HHH));
    op[((0 * EE + e) * HHH + j0) >> 2] = a0;
    op[((1 * EE + e) * HHH + j0) >> 2] = a1;
    op[((2 * EE + e) * HHH + j0) >> 2] = a2;
    op[((3 * EE + e) * HHH + j0) >> 2] = a3;
}

// ---------------- 7. MLP2 partial: grid (32 e, 32 hc), 256 thr -------------
// (h dc-reduce + b1 + gelu fused into prologue)
__global__ void k_mlp2(const float* __restrict__ w2, const float* __restrict__ b1) {
    __shared__ float hs[4][128];
    int e = blockIdx.x, hc = blockIdx.y, t = threadIdx.x;
    #pragma unroll
    for (int k = 0; k < 2; k++) {
        int idx = t + k * 256;
        int b = idx >> 7, j = idx & 127;
        int jg = hc * 128 + j;
        float s = b1[e * HHH + jg];
        #pragma unroll
        for (int dcc = 0; dcc < 8; dcc++)
            s += g_h_part[(size_t)dcc * (BB * EE * HHH) + (b * EE + e) * HHH + jg];
        hs[b][j] = gelu_exact(s);
    }
    __syncthreads();
    int d0 = t * 4;
    const float4* wp = (const float4*)(w2 + ((size_t)e * HHH + hc * 128) * DD + d0);
    float4 a0 = {0,0,0,0}, a1 = {0,0,0,0}, a2 = {0,0,0,0}, a3 = {0,0,0,0};
    #pragma unroll 16
    for (int hh = 0; hh < 128; hh++) {
        float4 w = __ldcs(&wp[(size_t)hh * (DD / 4)]);
        float h0 = hs[0][hh], h1 = hs[1][hh], h2 = hs[2][hh], h3 = hs[3][hh];
        a0.x += h0 * w.x; a0.y += h0 * w.y; a0.z += h0 * w.z; a0.w += h0 * w.w;
        a1.x += h1 * w.x; a1.y += h1 * w.y; a1.z += h1 * w.z; a1.w += h1 * w.w;
        a2.x += h2 * w.x; a2.y += h2 * w.y; a2.z += h2 * w.z; a2.w += h2 * w.w;
        a3.x += h3 * w.x; a3.y += h3 * w.y; a3.z += h3 * w.z; a3.w += h3 * w.w;
    }
    float4* op = (float4*)(g_eout_part + (size_t)hc * (BB * EE * DD));
    op[((0 * EE + e) * DD + d0) >> 2] = a0;
    op[((1 * EE + e) * DD + d0) >> 2] = a1;
    op[((2 * EE + e) * DD + d0) >> 2] = a2;
    op[((3 * EE + e) * DD + d0) >> 2] = a3;
}

// ---------------- 7b. eout = sum_hc eout_part + b2 --------------------------
__global__ void k_eout_reduce(const float* __restrict__ b2) {
    int i4 = blockIdx.x * 256 + threadIdx.x;   // 32768 float4s
    float4 acc = {0, 0, 0, 0};
    #pragma unroll
    for (int c = 0; c < 32; c++) {
        float4 v = ((const float4*)(g_eout_part + (size_t)c * (BB * EE * DD)))[i4];
        acc.x += v.x; acc.y += v.y; acc.z += v.z; acc.w += v.w;
    }
    int i = i4 << 2;
    int e = (i >> 10) & 31, d = i & 1023;
    float4 bb = *(const float4*)(b2 + e * DD + d);
    acc.x += bb.x; acc.y += bb.y; acc.z += bb.z; acc.w += bb.w;
    ((float4*)g_eout)[i4] = acc;
}

// ---------------- 8. out[b,n,d] = sum_e combine[b,n,e]*eout[b,e,d] --------
__global__ void k_out(float* __restrict__ out) {
    __shared__ float eo[32][256];
    __shared__ float cw[64][32];
    int b = blockIdx.x, nt = blockIdx.y, dt = blockIdx.z, t = threadIdx.x;
    #pragma unroll
    for (int k = 0; k < 32; k++) {
        int idx = t + k * 256;
        int e = idx >> 8, c = idx & 255;
        eo[e][c] = g_eout[(b * EE + e) * DD + dt * 256 + c];
    }
    #pragma unroll
    for (int k = 0; k < 8; k++) {
        int idx = t + k * 256;
        int r = idx >> 5, c = idx & 31;
        cw[r][c] = g_combine[(((b << 10) + nt * 64 + r) << 5) + c];
    }
    __syncthreads();
    int d = dt * 256 + t;
    for (int n = 0; n < 64; n++) {
        float a = 0.f;
        #pragma unroll
        for (int e = 0; e < 32; e++) a += cw[n][e] * eo[e][t];
        out[(((b << 10) + nt * 64 + n) << 10) + d] = a;
    }
}

// ---------------- 9. metrics finalization -----------------
__global__ void k_final(float* __restrict__ out, int out_size) {
    int t = threadIdx.x;
    float a = g_part_cw1[t];
    float b = g_part_cw2[t];
    float c = g_part_dw[t];
    a = blockSum(a);
    b = blockSum(b);
    c = blockSum(c);
    if (t == 0) {
        out[out_size - 2] = (a - b) / (float)(4.0 * 1024.0 * 1023.0);
        out[out_size - 1] = c / (float)(4 * 32 * 31);
    }
}

// ---------------- launch ----------------
extern "C" void kernel_launch(void* const* d_in, const int* in_sizes, int n_in,
                              void* d_out, int out_size) {
    const float* x   = (const float*)d_in[0];
    const float* phi = (const float*)d_in[1];
    const float* kg  = (const float*)d_in[2];
    const float* kb  = (const float*)d_in[3];
    const float* qg  = (const float*)d_in[4];
    const float* qb  = (const float*)d_in[5];
    const float* lg  = (const float*)d_in[6];
    const float* lb  = (const float*)d_in[7];
    const float* sc  = (const float*)d_in[8];
    const float* w1  = (const float*)d_in[9];
    const float* b1  = (const float*)d_in[10];
    const float* w2  = (const float*)d_in[11];
    const float* b2  = (const float*)d_in[12];
    float* out = (float*)d_out;

    k_query<<<32, 256>>>(phi, qg, qb, lg, lb, sc);
    k_logits<<<64, 256>>>(x, kg, kb);
    k_combine_sm<<<128, 1024>>>();
    k_dispatch_sm<<<128, 256>>>();
    k_slots<<<dim3(4, 16, 4), 256>>>(x);
    k_mlp1<<<dim3(32, 4, 8), 256>>>(w1);
    k_mlp2<<<dim3(32, 32), 256>>>(w2, b1);
    k_eout_reduce<<<128, 256>>>(b2);
    k_out<<<dim3(4, 16, 4), 256>>>(out);
    k_final<<<1, 128>>>(out, out_size);
}

// round 12
// speedup vs baseline: 2.7720x; 1.0217x over previous
#include <cuda_runtime.h>
#include <math.h>

#define BB 4
#define NN 1024
#define DD 1024
#define EE 32
#define HHH 4096

// ---------------- scratch (device globals; no allocation allowed) ----------
__device__ float g_logits[BB * NN * EE];            // 512 KB  [b,n,e]
__device__ float g_logitsT[BB * EE * NN];           // 512 KB  [b,e,n]
__device__ float g_combine[BB * NN * EE];           // 512 KB  [b,n,e]
__device__ float g_dispT[BB * EE * NN];             // 512 KB  [b,e,n]
__device__ float g_slots_part[4 * BB * EE * DD];    // 2 MB
__device__ float g_h[BB * EE * HHH];                // 2 MB
__device__ float g_eout_part[32 * BB * EE * DD];    // 16 MB
__device__ float g_eout[BB * EE * DD];              // 512 KB
__device__ float g_part_cw1[128];
__device__ float g_part_cw2[128];
__device__ float g_part_dw[128];

// ---------------- reduction helpers ----------------
__device__ __forceinline__ float warpSum(float v) {
    #pragma unroll
    for (int o = 16; o; o >>= 1) v += __shfl_xor_sync(0xffffffffu, v, o);
    return v;
}
__device__ __forceinline__ float warpMax(float v) {
    #pragma unroll
    for (int o = 16; o; o >>= 1) v = fmaxf(v, __shfl_xor_sync(0xffffffffu, v, o));
    return v;
}
__device__ float blockSum(float v) {
    __shared__ float sh[32];
    int lane = threadIdx.x & 31, wid = threadIdx.x >> 5;
    int nw = (blockDim.x + 31) >> 5;
    v = warpSum(v);
    if (lane == 0) sh[wid] = v;
    __syncthreads();
    float r = (threadIdx.x < (unsigned)nw) ? sh[threadIdx.x] : 0.f;
    if (wid == 0) {
        r = warpSum(r);
        if (lane == 0) sh[0] = r;
    }
    __syncthreads();
    r = sh[0];
    __syncthreads();
    return r;
}
__device__ float blockMax(float v) {
    __shared__ float sh[32];
    int lane = threadIdx.x & 31, wid = threadIdx.x >> 5;
    int nw = (blockDim.x + 31) >> 5;
    v = warpMax(v);
    if (lane == 0) sh[wid] = v;
    __syncthreads();
    float r = (threadIdx.x < (unsigned)nw) ? sh[threadIdx.x] : -INFINITY;
    if (wid == 0) {
        r = warpMax(r);
        if (lane == 0) sh[0] = r;
    }
    __syncthreads();
    r = sh[0];
    __syncthreads();
    return r;
}

__device__ __forceinline__ float gelu_exact(float x) {
    return 0.5f * x * (1.f + erff(x * 0.70710678118654752f));
}

// ---------------- 1. fused query-LN + logits --------------------------------
// Each block recomputes LN stats for all 32 experts (phi is L2-hot), then
// does the smem-tiled GEMM logits[b,n,e] = sum_d (x*kg+kb)*q[e,d].
__global__ void k_logits_q(const float* __restrict__ x, const float* __restrict__ phi,
                           const float* __restrict__ kg, const float* __restrict__ kb,
                           const float* __restrict__ qg, const float* __restrict__ qb,
                           const float* __restrict__ lg, const float* __restrict__ lb,
                           const float* __restrict__ sc) {
    __shared__ float xs[64][64];
    __shared__ float qs[32][65];
    __shared__ float ts[64][33];
    __shared__ float s_mean[32], s_rs[32];
    int t = threadIdx.x;
    int b = blockIdx.x >> 4, nb = (blockIdx.x & 15) * 64;
    int e = t & 31, ng = t >> 5;
    int lane = t & 31, w = t >> 5;

    // LN stats: warp w handles experts w*4..w*4+3
    #pragma unroll
    for (int i = 0; i < 4; i++) {
        int ee = w * 4 + i;
        float s = 0.f, s2 = 0.f;
        #pragma unroll 8
        for (int k = 0; k < 32; k++) {
            int d = k * 32 + lane;
            float y = phi[ee * DD + d] * qg[d] + qb[d];
            s += y; s2 += y * y;
        }
        s = warpSum(s); s2 = warpSum(s2);
        if (lane == 0) {
            float m = s * (1.f / DD);
            s_mean[ee] = m;
            s_rs[ee] = rsqrtf(s2 * (1.f / DD) - m * m + 1e-5f);
        }
    }
    __syncthreads();
    float scale = sc[0];

    float acc[8] = {0, 0, 0, 0, 0, 0, 0, 0};
    for (int dc = 0; dc < 16; dc++) {
        int dbase = dc * 64;
        #pragma unroll
        for (int k = 0; k < 16; k++) {
            int idx = t + k * 256;
            int r = idx >> 6, c = idx & 63, d = dbase + c;
            xs[r][c] = x[((b << 10) + nb + r) * DD + d] * kg[d] + kb[d];
        }
        #pragma unroll
        for (int k = 0; k < 8; k++) {
            int idx = t + k * 256;
            int r = idx >> 6, c = idx & 63, d = dbase + c;
            float y = phi[r * DD + d] * qg[d] + qb[d];
            qs[r][c] = ((y - s_mean[r]) * s_rs[r] * lg[d] + lb[d]) * scale;
        }
        __syncthreads();
        #pragma unroll 4
        for (int dd = 0; dd < 64; dd++) {
            float qv = qs[e][dd];
            #pragma unroll
            for (int i = 0; i < 8; i++) acc[i] += xs[ng * 8 + i][dd] * qv;
        }
        __syncthreads();
    }
    #pragma unroll
    for (int i = 0; i < 8; i++) {
        g_logits[(((b << 10) + nb + ng * 8 + i) << 5) + e] = acc[i];
        ts[ng * 8 + i][e] = acc[i];
    }
    __syncthreads();
    #pragma unroll
    for (int k = 0; k < 8; k++) {
        int idx = t + k * 256;
        int ee = idx >> 6, n = idx & 63;
        g_logitsT[(((b << 5) + ee) << 10) + nb + n] = ts[n][ee];
    }
}

// ---------------- 2. dispatch softmax over N (coalesced) -------------------
__global__ void k_dispatch_sm() {
    int be = blockIdx.x;          // be = b*32 + e
    int e = be & 31;
    int t = threadIdx.x;
    float v[4];
    float mx = -INFINITY;
    #pragma unroll
    for (int k = 0; k < 4; k++) {
        int n = t + k * 256;
        v[k] = g_logitsT[(be << 10) + n];
        mx = fmaxf(mx, v[k]);
    }
    mx = blockMax(mx);
    float ls = 0.f;
    #pragma unroll
    for (int k = 0; k < 4; k++) { v[k] = expf(v[k] - mx); ls += v[k]; }
    float S = blockSum(ls);
    float inv = 1.f / S;
    float s1 = 0.f, s2 = 0.f;
    #pragma unroll
    for (int k = 0; k < 4; k++) {
        int n = t + k * 256;
        float dv = v[k] * inv;
        g_dispT[(be << 10) + n] = dv;
        s1 += dv;
        s2 += dv * dv;
    }
    float S1 = blockSum(s1);
    float S2 = blockSum(s2);
    if (t == 0) {
        float rsd = rsqrtf(S2 + 1e-9f);
        float sn = S1 * rsd;
        g_part_dw[be] = (e == 0) ? 0.f : sn * sn;
    }
}

// ---------------- 3. slots partials: sum_n dispT[b,e,n]*x[b,n,d] -----------
__global__ void k_slots(const float* __restrict__ x) {
    __shared__ float ws[64][33];
    int b = blockIdx.x, dt = blockIdx.y, nc = blockIdx.z;
    int t = threadIdx.x;
    int d = dt * 64 + (t & 63);
    int eb = (t >> 6) * 8;
    float acc[8] = {0, 0, 0, 0, 0, 0, 0, 0};
    for (int no = 0; no < 4; no++) {
        int nbase = nc * 256 + no * 64;
        #pragma unroll
        for (int k = 0; k < 8; k++) {
            int idx = t + k * 256;
            int ee = idx >> 6, n = idx & 63;
            ws[n][ee] = g_dispT[(((b << 5) + ee) << 10) + nbase + n];
        }
        __syncthreads();
        #pragma unroll 4
        for (int nn = 0; nn < 64; nn++) {
            float xv = __ldg(&x[(((b << 10) + nbase + nn) << 10) + d]);
            #pragma unroll
            for (int i = 0; i < 8; i++) acc[i] += ws[nn][eb + i] * xv;
        }
        __syncthreads();
    }
    #pragma unroll
    for (int i = 0; i < 8; i++)
        g_slots_part[nc * (BB * EE * DD) + (b * EE + eb + i) * DD + d] = acc[i];
}

// ---------------- 4. MLP1: h = gelu(slots @ w1 + b1), direct write ---------
// grid (32 e, 32 jt of 128), 256 thr. Warp dg handles d = dg mod 8;
// cross-warp reduce in smem, then b1 + gelu epilogue.
__global__ void k_mlp1(const float* __restrict__ w1, const float* __restrict__ b1) {
    __shared__ float ss[4][1024];                 // 16 KB
    __shared__ float4 red[8][32][4];              // 16 KB
    int e = blockIdx.x, jt = blockIdx.y, t = threadIdx.x;
    // prologue: fuse slots nc-reduce (slots_part is L2-resident)
    #pragma unroll
    for (int k = 0; k < 16; k++) {
        int idx = t + k * 256;
        int b = idx >> 10, d = idx & 1023;
        float s = 0.f;
        #pragma unroll
        for (int nc = 0; nc < 4; nc++)
            s += g_slots_part[nc * (BB * EE * DD) + (b * EE + e) * DD + d];
        ss[b][d] = s;
    }
    __syncthreads();
    int lane = t & 31, dg = t >> 5;
    int j = jt * 128 + lane * 4;
    const float* wbase = w1 + (size_t)e * DD * HHH;
    float4 a0 = {0,0,0,0}, a1 = {0,0,0,0}, a2 = {0,0,0,0}, a3 = {0,0,0,0};
    #pragma unroll 8
    for (int d = dg; d < 1024; d += 8) {
        float4 w = __ldcs((const float4*)(wbase + (size_t)d * HHH + j));
        float s0 = ss[0][d], s1 = ss[1][d], s2 = ss[2][d], s3 = ss[3][d];
        a0.x += s0 * w.x; a0.y += s0 * w.y; a0.z += s0 * w.z; a0.w += s0 * w.w;
        a1.x += s1 * w.x; a1.y += s1 * w.y; a1.z += s1 * w.z; a1.w += s1 * w.w;
        a2.x += s2 * w.x; a2.y += s2 * w.y; a2.z += s2 * w.z; a2.w += s2 * w.w;
        a3.x += s3 * w.x; a3.y += s3 * w.y; a3.z += s3 * w.z; a3.w += s3 * w.w;
    }
    red[dg][lane][0] = a0;
    red[dg][lane][1] = a1;
    red[dg][lane][2] = a2;
    red[dg][lane][3] = a3;
    __syncthreads();
    if (t < 128) {
        int b = t >> 5, jq = t & 31;
        float4 r = {0,0,0,0};
        #pragma unroll
        for (int g = 0; g < 8; g++) {
            float4 v = red[g][jq][b];
            r.x += v.x; r.y += v.y; r.z += v.z; r.w += v.w;
        }
        int jg = jt * 128 + jq * 4;
        float4 bb = *(const float4*)(b1 + e * HHH + jg);
        float4 o;
        o.x = gelu_exact(r.x + bb.x);
        o.y = gelu_exact(r.y + bb.y);
        o.z = gelu_exact(r.z + bb.z);
        o.w = gelu_exact(r.w + bb.w);
        *(float4*)(g_h + (size_t)(b * EE + e) * HHH + jg) = o;
    }
}

// ---------------- 5. combine softmax + cw metric partials ------------------
__global__ void k_combine_sm() {
    int t = threadIdx.x, lane = t & 31, w = t >> 5;
    int row = blockIdx.x * 32 + w;
    float v = g_logits[(row << 5) + lane];
    float m = warpMax(v);
    float p = expf(v - m);
    float s = warpSum(p);
    float cw = p / s;
    g_combine[(row << 5) + lane] = cw;
    float s2 = warpSum(cw * cw);
    float rs = rsqrtf(s2 + 1e-9f);
    float cf = cw * rs;
    float s1 = warpSum(cf);
    int n = row & 1023;
    float c2 = (n < 32 && lane == n) ? cf * s1 : 0.f;
    c2 = warpSum(c2);
    __shared__ float p1[32], p2[32];
    if (lane == 0) { p1[w] = s1 * s1; p2[w] = c2; }
    __syncthreads();
    if (w == 0) {
        float a = warpSum(p1[lane]);
        float bb2 = warpSum(p2[lane]);
        if (lane == 0) { g_part_cw1[blockIdx.x] = a; g_part_cw2[blockIdx.x] = bb2; }
    }
}

// ---------------- 6. MLP2 partial: grid (32 e, 32 hc), 256 thr -------------
// prologue reads g_h (L2-hot, gelu already applied)
__global__ void k_mlp2(const float* __restrict__ w2) {
    __shared__ float hs[4][128];
    int e = blockIdx.x, hc = blockIdx.y, t = threadIdx.x;
    #pragma unroll
    for (int k = 0; k < 2; k++) {
        int idx = t + k * 256;
        int b = idx >> 7, j = idx & 127;
        hs[b][j] = g_h[(size_t)(b * EE + e) * HHH + hc * 128 + j];
    }
    __syncthreads();
    int d0 = t * 4;
    const float4* wp = (const float4*)(w2 + ((size_t)e * HHH + hc * 128) * DD + d0);
    float4 a0 = {0,0,0,0}, a1 = {0,0,0,0}, a2 = {0,0,0,0}, a3 = {0,0,0,0};
    #pragma unroll 16
    for (int hh = 0; hh < 128; hh++) {
        float4 w = __ldcs(&wp[(size_t)hh * (DD / 4)]);
        float h0 = hs[0][hh], h1 = hs[1][hh], h2 = hs[2][hh], h3 = hs[3][hh];
        a0.x += h0 * w.x; a0.y += h0 * w.y; a0.z += h0 * w.z; a0.w += h0 * w.w;
        a1.x += h1 * w.x; a1.y += h1 * w.y; a1.z += h1 * w.z; a1.w += h1 * w.w;
        a2.x += h2 * w.x; a2.y += h2 * w.y; a2.z += h2 * w.z; a2.w += h2 * w.w;
        a3.x += h3 * w.x; a3.y += h3 * w.y; a3.z += h3 * w.z; a3.w += h3 * w.w;
    }
    float4* op = (float4*)(g_eout_part + (size_t)hc * (BB * EE * DD));
    op[((0 * EE + e) * DD + d0) >> 2] = a0;
    op[((1 * EE + e) * DD + d0) >> 2] = a1;
    op[((2 * EE + e) * DD + d0) >> 2] = a2;
    op[((3 * EE + e) * DD + d0) >> 2] = a3;
}

// ---------------- 7. eout = sum_hc eout_part + b2 --------------------------
__global__ void k_eout_reduce(const float* __restrict__ b2) {
    int i4 = blockIdx.x * 256 + threadIdx.x;   // 32768 float4s
    float4 acc = {0, 0, 0, 0};
    #pragma unroll
    for (int c = 0; c < 32; c++) {
        float4 v = ((const float4*)(g_eout_part + (size_t)c * (BB * EE * DD)))[i4];
        acc.x += v.x; acc.y += v.y; acc.z += v.z; acc.w += v.w;
    }
    int i = i4 << 2;
    int e = (i >> 10) & 31, d = i & 1023;
    float4 bb = *(const float4*)(b2 + e * DD + d);
    acc.x += bb.x; acc.y += bb.y; acc.z += bb.z; acc.w += bb.w;
    ((float4*)g_eout)[i4] = acc;
}

// ---------------- 8. out = combine @ eout, + metrics finalization ----------
__global__ void k_out(float* __restrict__ out, int out_size) {
    __shared__ float eo[32][256];
    __shared__ float cw[64][32];
    int b = blockIdx.x, nt = blockIdx.y, dt = blockIdx.z, t = threadIdx.x;
    #pragma unroll
    for (int k = 0; k < 32; k++) {
        int idx = t + k * 256;
        int e = idx >> 8, c = idx & 255;
        eo[e][c] = g_eout[(b * EE + e) * DD + dt * 256 + c];
    }
    #pragma unroll
    for (int k = 0; k < 8; k++) {
        int idx = t + k * 256;
        int r = idx >> 5, c = idx & 31;
        cw[r][c] = g_combine[(((b << 10) + nt * 64 + r) << 5) + c];
    }
    __syncthreads();
    int d = dt * 256 + t;
    for (int n = 0; n < 64; n++) {
        float a = 0.f;
        #pragma unroll
        for (int e = 0; e < 32; e++) a += cw[n][e] * eo[e][t];
        out[(((b << 10) + nt * 64 + n) << 10) + d] = a;
    }
    // metrics finalization in block 0 (all deps done before this kernel)
    if (blockIdx.x == 0 && blockIdx.y == 0 && blockIdx.z == 0) {
        float a = (t < 128) ? g_part_cw1[t] : 0.f;
        float bb = (t < 128) ? g_part_cw2[t] : 0.f;
        float c = (t < 128) ? g_part_dw[t] : 0.f;
        a = blockSum(a);
        bb = blockSum(bb);
        c = blockSum(c);
        if (t == 0) {
            out[out_size - 2] = (a - bb) / (float)(4.0 * 1024.0 * 1023.0);
            out[out_size - 1] = c / (float)(4 * 32 * 31);
        }
    }
}

// ---------------- launch ----------------
extern "C" void kernel_launch(void* const* d_in, const int* in_sizes, int n_in,
                              void* d_out, int out_size) {
    const float* x   = (const float*)d_in[0];
    const float* phi = (const float*)d_in[1];
    const float* kg  = (const float*)d_in[2];
    const float* kb  = (const float*)d_in[3];
    const float* qg  = (const float*)d_in[4];
    const float* qb  = (const float*)d_in[5];
    const float* lg  = (const float*)d_in[6];
    const float* lb  = (const float*)d_in[7];
    const float* sc  = (const float*)d_in[8];
    const float* w1  = (const float*)d_in[9];
    const float* b1  = (const float*)d_in[10];
    const float* w2  = (const float*)d_in[11];
    const float* b2  = (const float*)d_in[12];
    float* out = (float*)d_out;

    k_logits_q<<<64, 256>>>(x, phi, kg, kb, qg, qb, lg, lb, sc);  // 1
    k_dispatch_sm<<<128, 256>>>();                                 // 2
    k_slots<<<dim3(4, 16, 4), 256>>>(x);                           // 3
    k_mlp1<<<dim3(32, 32), 256>>>(w1, b1);                         // 4  <- ncu capture slot
    k_combine_sm<<<128, 1024>>>();                                 // 5
    k_mlp2<<<dim3(32, 32), 256>>>(w2);                             // 6
    k_eout_reduce<<<128, 256>>>(b2);                               // 7
    k_out<<<dim3(4, 16, 4), 256>>>(out, out_size);                 // 8
}